// round 3
// baseline (speedup 1.0000x reference)
#include <cuda_runtime.h>
#include <math.h>

#define N 8192
#define KD 32

// -9.010913347279288 = -log(8192)
#define LOGMU (-9.0109133f)
#define LOGNU (-9.0109133f)

// Scratch (allocation-free: device globals)
__device__ float d_C[(size_t)N * N];        // 256 MB cost matrix
__device__ float d_f[N];
__device__ float d_g[N];
__device__ float d_pm[64 * N];              // column-LSE partial max
__device__ float d_ps[64 * N];              // column-LSE partial sum

// ---------------------------------------------------------------------------
// Kernel 1: build C = |x_i|^2 + |y_j|^2 - 2 x_i.y_j  (128x128 tiles, 8x8/thread)
// Also zeroes d_g and the output scalar.
// ---------------------------------------------------------------------------
__global__ __launch_bounds__(256) void compute_c_kernel(
    const float* __restrict__ x, const float* __restrict__ y,
    float* __restrict__ out)
{
    __shared__ float xsT[KD][129];   // [k][row], padded to kill STS conflicts
    __shared__ float ysT[KD][129];
    __shared__ float xn[128];
    __shared__ float yn[128];

    const int tid = threadIdx.x;
    const int bx = blockIdx.x, by = blockIdx.y;
    const int row0 = by * 128, col0 = bx * 128;

    // init duties (first 32 blocks zero g; block 0 thread 0 zeroes out)
    {
        int gid = (by * gridDim.x + bx) * 256 + tid;
        if (gid < N) d_g[gid] = 0.0f;
        if (gid == 0) out[0] = 0.0f;
    }

    // load tiles (transposed into smem): 1024 float4 each
    const float4* x4 = (const float4*)(x + (size_t)row0 * KD);
    const float4* y4 = (const float4*)(y + (size_t)col0 * KD);
#pragma unroll
    for (int it = 0; it < 4; ++it) {
        int f = tid + it * 256;          // 0..1023
        int r = f >> 3;
        int k = (f & 7) * 4;
        float4 vx = x4[f];
        xsT[k + 0][r] = vx.x; xsT[k + 1][r] = vx.y;
        xsT[k + 2][r] = vx.z; xsT[k + 3][r] = vx.w;
        float4 vy = y4[f];
        ysT[k + 0][r] = vy.x; ysT[k + 1][r] = vy.y;
        ysT[k + 2][r] = vy.z; ysT[k + 3][r] = vy.w;
    }
    __syncthreads();

    // squared norms
    if (tid < 128) {
        float s = 0.0f;
#pragma unroll
        for (int k = 0; k < KD; ++k) { float a = xsT[k][tid]; s = fmaf(a, a, s); }
        xn[tid] = s;
    } else {
        int r = tid - 128;
        float s = 0.0f;
#pragma unroll
        for (int k = 0; k < KD; ++k) { float a = ysT[k][r]; s = fmaf(a, a, s); }
        yn[r] = s;
    }
    __syncthreads();

    const int tx = tid & 15;   // column direction
    const int ty = tid >> 4;   // row direction

    float acc[8][8];
#pragma unroll
    for (int i = 0; i < 8; ++i)
#pragma unroll
        for (int j = 0; j < 8; ++j) acc[i][j] = 0.0f;

#pragma unroll
    for (int k = 0; k < KD; ++k) {
        float a[8], b[8];
#pragma unroll
        for (int u = 0; u < 8; ++u) a[u] = xsT[k][ty * 8 + u];
#pragma unroll
        for (int u = 0; u < 8; ++u) b[u] = ysT[k][tx * 8 + u];
#pragma unroll
        for (int i = 0; i < 8; ++i)
#pragma unroll
            for (int j = 0; j < 8; ++j)
                acc[i][j] = fmaf(a[i], b[j], acc[i][j]);
    }

    float ynr[8];
#pragma unroll
    for (int j = 0; j < 8; ++j) ynr[j] = yn[tx * 8 + j];

#pragma unroll
    for (int i = 0; i < 8; ++i) {
        int r = row0 + ty * 8 + i;
        float xni = xn[ty * 8 + i];
        float4* crow = (float4*)(d_C + (size_t)r * N + col0 + tx * 8);
        float4 o0, o1;
        o0.x = xni + ynr[0] - 2.0f * acc[i][0];
        o0.y = xni + ynr[1] - 2.0f * acc[i][1];
        o0.z = xni + ynr[2] - 2.0f * acc[i][2];
        o0.w = xni + ynr[3] - 2.0f * acc[i][3];
        o1.x = xni + ynr[4] - 2.0f * acc[i][4];
        o1.y = xni + ynr[5] - 2.0f * acc[i][5];
        o1.z = xni + ynr[6] - 2.0f * acc[i][6];
        o1.w = xni + ynr[7] - 2.0f * acc[i][7];
        crow[0] = o0;
        crow[1] = o1;
    }
}

// ---------------------------------------------------------------------------
// Kernel 2: f_i = LOGMU - lse_j( g_j - C_ij )   (one block per row)
// ---------------------------------------------------------------------------
__global__ __launch_bounds__(256) void f_kernel()
{
    __shared__ float v[N];       // 32 KB row buffer
    __shared__ float redm[8];
    __shared__ float reds[8];

    const int tid = threadIdx.x;
    const int row = blockIdx.x;

    const float4* C4 = (const float4*)(d_C + (size_t)row * N);
    const float4* g4 = (const float4*)d_g;
    float4* v4 = (float4*)v;

    float m = -INFINITY;
#pragma unroll
    for (int it = 0; it < 8; ++it) {
        int i = tid + it * 256;
        float4 c = C4[i];
        float4 g = g4[i];
        float4 w;
        w.x = g.x - c.x; w.y = g.y - c.y; w.z = g.z - c.z; w.w = g.w - c.w;
        v4[i] = w;
        m = fmaxf(m, fmaxf(fmaxf(w.x, w.y), fmaxf(w.z, w.w)));
    }
#pragma unroll
    for (int o = 16; o > 0; o >>= 1) m = fmaxf(m, __shfl_xor_sync(0xffffffffu, m, o));
    if ((tid & 31) == 0) redm[tid >> 5] = m;
    __syncthreads();
    float bm = redm[0];
#pragma unroll
    for (int w = 1; w < 8; ++w) bm = fmaxf(bm, redm[w]);

    float s = 0.0f;
#pragma unroll
    for (int it = 0; it < 8; ++it) {
        float4 w = v4[tid + it * 256];
        s += __expf(w.x - bm) + __expf(w.y - bm) + __expf(w.z - bm) + __expf(w.w - bm);
    }
#pragma unroll
    for (int o = 16; o > 0; o >>= 1) s += __shfl_xor_sync(0xffffffffu, s, o);
    if ((tid & 31) == 0) reds[tid >> 5] = s;
    __syncthreads();
    if (tid == 0) {
        float tot = reds[0];
#pragma unroll
        for (int w = 1; w < 8; ++w) tot += reds[w];
        d_f[row] = LOGMU - (bm + __logf(tot));
    }
}

// ---------------------------------------------------------------------------
// Kernel 3: column-LSE partials:   (m,s) over 128-row chunk for each column
//           lse_i( f_i - C_ij )  via online (flash-style) update
// ---------------------------------------------------------------------------
__global__ __launch_bounds__(128) void g_partial_kernel()
{
    const int tid = threadIdx.x;                 // 128 threads = 128 columns
    const int j = blockIdx.x * 128 + tid;
    const int i0 = blockIdx.y * 128;

    __shared__ float fs[128];
    fs[tid] = d_f[i0 + tid];
    __syncthreads();

    const float* Cp = d_C + (size_t)i0 * N + j;

    float m = -INFINITY, s = 0.0f;
#pragma unroll 4
    for (int r = 0; r < 128; ++r) {
        float vv = fs[r] - Cp[(size_t)r * N];
        if (vv > m) { s *= __expf(m - vv); m = vv; }
        s += __expf(vv - m);
    }
    d_pm[(size_t)blockIdx.y * N + j] = m;
    d_ps[(size_t)blockIdx.y * N + j] = s;
}

// ---------------------------------------------------------------------------
// Kernel 4: combine 64 (m,s) partials per column -> g_j
// ---------------------------------------------------------------------------
__global__ __launch_bounds__(128) void g_combine_kernel()
{
    const int j = blockIdx.x * 128 + threadIdx.x;
    float m = -INFINITY, s = 0.0f;
#pragma unroll 4
    for (int k = 0; k < 64; ++k) {
        float mm = d_pm[(size_t)k * N + j];
        float ss = d_ps[(size_t)k * N + j];
        if (mm > m) { s = s * __expf(m - mm) + ss; m = mm; }
        else        { s += ss * __expf(mm - m); }
    }
    d_g[j] = LOGNU - (m + __logf(s));
}

// ---------------------------------------------------------------------------
// Kernel 5: loss = sum_ij C_ij * exp(f_i + g_j - C_ij)  (one block per row)
// ---------------------------------------------------------------------------
__global__ __launch_bounds__(256) void loss_kernel(float* __restrict__ out)
{
    __shared__ float reds[8];
    const int tid = threadIdx.x;
    const int row = blockIdx.x;

    const float fi = d_f[row];
    const float4* C4 = (const float4*)(d_C + (size_t)row * N);
    const float4* g4 = (const float4*)d_g;

    float acc = 0.0f;
#pragma unroll
    for (int it = 0; it < 8; ++it) {
        int i = tid + it * 256;
        float4 c = C4[i];
        float4 g = g4[i];
        acc = fmaf(c.x, __expf(fi + g.x - c.x), acc);
        acc = fmaf(c.y, __expf(fi + g.y - c.y), acc);
        acc = fmaf(c.z, __expf(fi + g.z - c.z), acc);
        acc = fmaf(c.w, __expf(fi + g.w - c.w), acc);
    }
#pragma unroll
    for (int o = 16; o > 0; o >>= 1) acc += __shfl_xor_sync(0xffffffffu, acc, o);
    if ((tid & 31) == 0) reds[tid >> 5] = acc;
    __syncthreads();
    if (tid == 0) {
        float tot = reds[0];
#pragma unroll
        for (int w = 1; w < 8; ++w) tot += reds[w];
        atomicAdd(out, tot);
    }
}

// ---------------------------------------------------------------------------
extern "C" void kernel_launch(void* const* d_in, const int* in_sizes, int n_in,
                              void* d_out, int out_size)
{
    const float* x = (const float*)d_in[0];
    const float* y = (const float*)d_in[1];
    float* out = (float*)d_out;

    compute_c_kernel<<<dim3(64, 64), 256>>>(x, y, out);

    for (int t = 0; t < 10; ++t) {
        f_kernel<<<N, 256>>>();
        g_partial_kernel<<<dim3(64, 64), 128>>>();
        g_combine_kernel<<<64, 128>>>();
    }

    loss_kernel<<<N, 256>>>(out);
}

// round 5
// speedup vs baseline: 1.2114x; 1.2114x over previous
#include <cuda_runtime.h>
#include <cuda_fp16.h>
#include <math.h>

#define N 8192
#define KD 32

// -log(8192)
#define LOGMU (-9.0109133f)
#define LOGNU (-9.0109133f)

// Scratch (allocation-free: device globals)
__device__ __half d_C[(size_t)N * N];       // 128 MB cost matrix (fp16)
__device__ float  d_f[N];
__device__ float  d_g[N];
__device__ float2 d_p[(size_t)64 * N];      // column-LSE partials (m, s) interleaved

// ---------------------------------------------------------------------------
// Kernel 1: build C = |x_i|^2 + |y_j|^2 - 2 x_i.y_j  (128x128 tiles, 8x8/thread)
// Stores fp16. Also zeroes d_g and the output scalar.
// ---------------------------------------------------------------------------
__global__ __launch_bounds__(256) void compute_c_kernel(
    const float* __restrict__ x, const float* __restrict__ y,
    float* __restrict__ out)
{
    __shared__ float xsT[KD][129];
    __shared__ float ysT[KD][129];
    __shared__ float xn[128];
    __shared__ float yn[128];

    const int tid = threadIdx.x;
    const int bx = blockIdx.x, by = blockIdx.y;
    const int row0 = by * 128, col0 = bx * 128;

    {
        int gid = (by * gridDim.x + bx) * 256 + tid;
        if (gid < N) d_g[gid] = 0.0f;
        if (gid == 0) out[0] = 0.0f;
    }

    const float4* x4 = (const float4*)(x + (size_t)row0 * KD);
    const float4* y4 = (const float4*)(y + (size_t)col0 * KD);
#pragma unroll
    for (int it = 0; it < 4; ++it) {
        int f = tid + it * 256;
        int r = f >> 3;
        int k = (f & 7) * 4;
        float4 vx = x4[f];
        xsT[k + 0][r] = vx.x; xsT[k + 1][r] = vx.y;
        xsT[k + 2][r] = vx.z; xsT[k + 3][r] = vx.w;
        float4 vy = y4[f];
        ysT[k + 0][r] = vy.x; ysT[k + 1][r] = vy.y;
        ysT[k + 2][r] = vy.z; ysT[k + 3][r] = vy.w;
    }
    __syncthreads();

    if (tid < 128) {
        float s = 0.0f;
#pragma unroll
        for (int k = 0; k < KD; ++k) { float a = xsT[k][tid]; s = fmaf(a, a, s); }
        xn[tid] = s;
    } else {
        int r = tid - 128;
        float s = 0.0f;
#pragma unroll
        for (int k = 0; k < KD; ++k) { float a = ysT[k][r]; s = fmaf(a, a, s); }
        yn[r] = s;
    }
    __syncthreads();

    const int tx = tid & 15;
    const int ty = tid >> 4;

    float acc[8][8];
#pragma unroll
    for (int i = 0; i < 8; ++i)
#pragma unroll
        for (int j = 0; j < 8; ++j) acc[i][j] = 0.0f;

#pragma unroll
    for (int k = 0; k < KD; ++k) {
        float a[8], b[8];
#pragma unroll
        for (int u = 0; u < 8; ++u) a[u] = xsT[k][ty * 8 + u];
#pragma unroll
        for (int u = 0; u < 8; ++u) b[u] = ysT[k][tx * 8 + u];
#pragma unroll
        for (int i = 0; i < 8; ++i)
#pragma unroll
            for (int j = 0; j < 8; ++j)
                acc[i][j] = fmaf(a[i], b[j], acc[i][j]);
    }

    float ynr[8];
#pragma unroll
    for (int j = 0; j < 8; ++j) ynr[j] = yn[tx * 8 + j];

#pragma unroll
    for (int i = 0; i < 8; ++i) {
        int r = row0 + ty * 8 + i;
        float xni = xn[ty * 8 + i];
        float c[8];
#pragma unroll
        for (int j = 0; j < 8; ++j) c[j] = xni + ynr[j] - 2.0f * acc[i][j];

        union { uint4 u; __half2 h[4]; } pk;
        pk.h[0] = __floats2half2_rn(c[0], c[1]);
        pk.h[1] = __floats2half2_rn(c[2], c[3]);
        pk.h[2] = __floats2half2_rn(c[4], c[5]);
        pk.h[3] = __floats2half2_rn(c[6], c[7]);
        *(uint4*)(d_C + (size_t)r * N + col0 + tx * 8) = pk.u;
    }
}

// ---------------------------------------------------------------------------
// Kernel 2: f_i = LOGMU - lse_j( g_j - C_ij )   (one block per row)
// C row loaded as half8, w = g - C cached fp32 in smem for the sum pass.
// ---------------------------------------------------------------------------
__global__ __launch_bounds__(256) void f_kernel()
{
    __shared__ float v[N];       // 32 KB
    __shared__ float redm[8];
    __shared__ float reds[8];

    const int tid = threadIdx.x;
    const int row = blockIdx.x;

    const uint4*  C8 = (const uint4*)(d_C + (size_t)row * N);   // 8 halves each
    const float4* g4 = (const float4*)d_g;
    float4* v4 = (float4*)v;

    float m = -INFINITY;
#pragma unroll
    for (int it = 0; it < 4; ++it) {
        int i = tid + it * 256;          // 0..1023 (half8 index)
        union { uint4 u; __half2 h[4]; } raw;
        raw.u = C8[i];
        float4 ga = g4[2 * i];
        float4 gb = g4[2 * i + 1];
        float2 c0 = __half22float2(raw.h[0]);
        float2 c1 = __half22float2(raw.h[1]);
        float2 c2 = __half22float2(raw.h[2]);
        float2 c3 = __half22float2(raw.h[3]);
        float4 w0, w1;
        w0.x = ga.x - c0.x; w0.y = ga.y - c0.y;
        w0.z = ga.z - c1.x; w0.w = ga.w - c1.y;
        w1.x = gb.x - c2.x; w1.y = gb.y - c2.y;
        w1.z = gb.z - c3.x; w1.w = gb.w - c3.y;
        v4[2 * i]     = w0;
        v4[2 * i + 1] = w1;
        m = fmaxf(m, fmaxf(fmaxf(w0.x, w0.y), fmaxf(w0.z, w0.w)));
        m = fmaxf(m, fmaxf(fmaxf(w1.x, w1.y), fmaxf(w1.z, w1.w)));
    }
#pragma unroll
    for (int o = 16; o > 0; o >>= 1) m = fmaxf(m, __shfl_xor_sync(0xffffffffu, m, o));
    if ((tid & 31) == 0) redm[tid >> 5] = m;
    __syncthreads();
    float bm = redm[0];
#pragma unroll
    for (int w = 1; w < 8; ++w) bm = fmaxf(bm, redm[w]);

    float s = 0.0f;
#pragma unroll
    for (int it = 0; it < 8; ++it) {
        float4 w = v4[tid + it * 256];
        s += __expf(w.x - bm) + __expf(w.y - bm) + __expf(w.z - bm) + __expf(w.w - bm);
    }
#pragma unroll
    for (int o = 16; o > 0; o >>= 1) s += __shfl_xor_sync(0xffffffffu, s, o);
    if ((tid & 31) == 0) reds[tid >> 5] = s;
    __syncthreads();
    if (tid == 0) {
        float tot = reds[0];
#pragma unroll
        for (int w = 1; w < 8; ++w) tot += reds[w];
        d_f[row] = LOGMU - (bm + __logf(tot));
    }
}

// ---------------------------------------------------------------------------
// Kernel 3: column-LSE partials. Each thread handles TWO columns (half2),
// online flash-style (m, s) over a 128-row chunk.
// grid (N/256, 64), block 128.
// ---------------------------------------------------------------------------
__global__ __launch_bounds__(128) void g_partial_kernel()
{
    const int tid = threadIdx.x;
    const int c2 = blockIdx.x * 128 + tid;       // half2 column index (2 cols)
    const int i0 = blockIdx.y * 128;

    __shared__ float fs[128];
    fs[tid] = d_f[i0 + tid];
    __syncthreads();

    const __half2* Cp = (const __half2*)(d_C + (size_t)i0 * N) + c2;

    float m0 = -INFINITY, s0 = 0.0f;
    float m1 = -INFINITY, s1 = 0.0f;
#pragma unroll 4
    for (int r = 0; r < 128; ++r) {
        float2 c = __half22float2(Cp[(size_t)r * (N / 2)]);
        float fr = fs[r];
        float v0 = fr - c.x;
        float v1 = fr - c.y;
        if (v0 > m0) { s0 *= __expf(m0 - v0); m0 = v0; }
        s0 += __expf(v0 - m0);
        if (v1 > m1) { s1 *= __expf(m1 - v1); m1 = v1; }
        s1 += __expf(v1 - m1);
    }
    float4* outp = (float4*)&d_p[(size_t)blockIdx.y * N + 2 * c2];
    float4 o; o.x = m0; o.y = s0; o.z = m1; o.w = s1;
    *outp = o;
}

// ---------------------------------------------------------------------------
// Kernel 4: combine 64 (m,s) partials per column -> g_j. One warp per column:
// lane merges partials (lane, lane+32), then 5-level shfl tree merge.
// grid 1024, block 256 (8 warps).
// ---------------------------------------------------------------------------
__global__ __launch_bounds__(256) void g_combine_kernel()
{
    const int lane = threadIdx.x & 31;
    const int wrp  = threadIdx.x >> 5;
    const int j = blockIdx.x * 8 + wrp;           // column

    float2 a = d_p[(size_t)lane * N + j];
    float2 b = d_p[(size_t)(lane + 32) * N + j];

    float m, s;
    if (a.x >= b.x) { m = a.x; s = a.y + b.y * __expf(b.x - a.x); }
    else            { m = b.x; s = b.y + a.y * __expf(a.x - b.x); }

#pragma unroll
    for (int o = 16; o > 0; o >>= 1) {
        float mo = __shfl_xor_sync(0xffffffffu, m, o);
        float so = __shfl_xor_sync(0xffffffffu, s, o);
        if (mo > m) { s = s * __expf(m - mo) + so; m = mo; }
        else        { s = s + so * __expf(mo - m); }
    }
    if (lane == 0) d_g[j] = LOGNU - (m + __logf(s));
}

// ---------------------------------------------------------------------------
// Kernel 5: loss = sum_ij C_ij * exp(f_i + g_j - C_ij)  (one block per row)
// ---------------------------------------------------------------------------
__global__ __launch_bounds__(256) void loss_kernel(float* __restrict__ out)
{
    __shared__ float reds[8];
    const int tid = threadIdx.x;
    const int row = blockIdx.x;

    const float fi = d_f[row];
    const uint4*  C8 = (const uint4*)(d_C + (size_t)row * N);
    const float4* g4 = (const float4*)d_g;

    float acc = 0.0f;
#pragma unroll
    for (int it = 0; it < 4; ++it) {
        int i = tid + it * 256;
        union { uint4 u; __half2 h[4]; } raw;
        raw.u = C8[i];
        float4 ga = g4[2 * i];
        float4 gb = g4[2 * i + 1];
        float2 c0 = __half22float2(raw.h[0]);
        float2 c1 = __half22float2(raw.h[1]);
        float2 c2 = __half22float2(raw.h[2]);
        float2 c3 = __half22float2(raw.h[3]);
        acc = fmaf(c0.x, __expf(fi + ga.x - c0.x), acc);
        acc = fmaf(c0.y, __expf(fi + ga.y - c0.y), acc);
        acc = fmaf(c1.x, __expf(fi + ga.z - c1.x), acc);
        acc = fmaf(c1.y, __expf(fi + ga.w - c1.y), acc);
        acc = fmaf(c2.x, __expf(fi + gb.x - c2.x), acc);
        acc = fmaf(c2.y, __expf(fi + gb.y - c2.y), acc);
        acc = fmaf(c3.x, __expf(fi + gb.z - c3.x), acc);
        acc = fmaf(c3.y, __expf(fi + gb.w - c3.y), acc);
    }
#pragma unroll
    for (int o = 16; o > 0; o >>= 1) acc += __shfl_xor_sync(0xffffffffu, acc, o);
    if ((tid & 31) == 0) reds[tid >> 5] = acc;
    __syncthreads();
    if (tid == 0) {
        float tot = reds[0];
#pragma unroll
        for (int w = 1; w < 8; ++w) tot += reds[w];
        atomicAdd(out, tot);
    }
}

// ---------------------------------------------------------------------------
extern "C" void kernel_launch(void* const* d_in, const int* in_sizes, int n_in,
                              void* d_out, int out_size)
{
    const float* x = (const float*)d_in[0];
    const float* y = (const float*)d_in[1];
    float* out = (float*)d_out;

    compute_c_kernel<<<dim3(64, 64), 256>>>(x, y, out);

    for (int t = 0; t < 10; ++t) {
        f_kernel<<<N, 256>>>();
        g_partial_kernel<<<dim3(N / 256, 64), 128>>>();
        g_combine_kernel<<<N / 8, 256>>>();
    }

    loss_kernel<<<N, 256>>>(out);
}

// round 6
// speedup vs baseline: 2.3559x; 1.9447x over previous
#include <cuda_runtime.h>
#include <cuda_bf16.h>
#include <math.h>

#define N 8192
#define KD 32

#define MUVAL (1.0f / 8192.0f)
#define NUVAL (1.0f / 8192.0f)

// Scratch (allocation-free: device globals)
__device__ __nv_bfloat16 d_K[(size_t)N * N];   // 128 MB: K = exp(-C) in bf16
__device__ float d_u[N];                        // u = exp(f)
__device__ float d_v[N];                        // v = exp(g)
__device__ float d_ps[(size_t)128 * N];         // column-sum partials
__device__ float d_pt[(size_t)128 * N];         // loss-sum partials (final iter)

// ---------------------------------------------------------------------------
// Kernel 1: build K = exp(-(|x_i|^2 + |y_j|^2 - 2 x_i.y_j)) in bf16.
// Also inits v = 1 and zeroes the output scalar.
// ---------------------------------------------------------------------------
__global__ __launch_bounds__(256) void build_k_kernel(
    const float* __restrict__ x, const float* __restrict__ y,
    float* __restrict__ out)
{
    __shared__ float xsT[KD][129];
    __shared__ float ysT[KD][129];
    __shared__ float xn[128];
    __shared__ float yn[128];

    const int tid = threadIdx.x;
    const int bx = blockIdx.x, by = blockIdx.y;
    const int row0 = by * 128, col0 = bx * 128;

    {
        int gid = (by * gridDim.x + bx) * 256 + tid;
        if (gid < N) d_v[gid] = 1.0f;
        if (gid == 0) out[0] = 0.0f;
    }

    const float4* x4 = (const float4*)(x + (size_t)row0 * KD);
    const float4* y4 = (const float4*)(y + (size_t)col0 * KD);
#pragma unroll
    for (int it = 0; it < 4; ++it) {
        int f = tid + it * 256;
        int r = f >> 3;
        int k = (f & 7) * 4;
        float4 vx = x4[f];
        xsT[k + 0][r] = vx.x; xsT[k + 1][r] = vx.y;
        xsT[k + 2][r] = vx.z; xsT[k + 3][r] = vx.w;
        float4 vy = y4[f];
        ysT[k + 0][r] = vy.x; ysT[k + 1][r] = vy.y;
        ysT[k + 2][r] = vy.z; ysT[k + 3][r] = vy.w;
    }
    __syncthreads();

    if (tid < 128) {
        float s = 0.0f;
#pragma unroll
        for (int k = 0; k < KD; ++k) { float a = xsT[k][tid]; s = fmaf(a, a, s); }
        xn[tid] = s;
    } else {
        int r = tid - 128;
        float s = 0.0f;
#pragma unroll
        for (int k = 0; k < KD; ++k) { float a = ysT[k][r]; s = fmaf(a, a, s); }
        yn[r] = s;
    }
    __syncthreads();

    const int tx = tid & 15;
    const int ty = tid >> 4;

    float acc[8][8];
#pragma unroll
    for (int i = 0; i < 8; ++i)
#pragma unroll
        for (int j = 0; j < 8; ++j) acc[i][j] = 0.0f;

#pragma unroll
    for (int k = 0; k < KD; ++k) {
        float a[8], b[8];
#pragma unroll
        for (int u = 0; u < 8; ++u) a[u] = xsT[k][ty * 8 + u];
#pragma unroll
        for (int u = 0; u < 8; ++u) b[u] = ysT[k][tx * 8 + u];
#pragma unroll
        for (int i = 0; i < 8; ++i)
#pragma unroll
            for (int j = 0; j < 8; ++j)
                acc[i][j] = fmaf(a[i], b[j], acc[i][j]);
    }

    float ynr[8];
#pragma unroll
    for (int j = 0; j < 8; ++j) ynr[j] = yn[tx * 8 + j];

#pragma unroll
    for (int i = 0; i < 8; ++i) {
        int r = row0 + ty * 8 + i;
        float xni = xn[ty * 8 + i];
        float kv[8];
#pragma unroll
        for (int j = 0; j < 8; ++j)
            kv[j] = __expf(2.0f * acc[i][j] - xni - ynr[j]);   // exp(-C)

        union { uint4 u; __nv_bfloat162 h[4]; } pk;
        pk.h[0] = __floats2bfloat162_rn(kv[0], kv[1]);
        pk.h[1] = __floats2bfloat162_rn(kv[2], kv[3]);
        pk.h[2] = __floats2bfloat162_rn(kv[4], kv[5]);
        pk.h[3] = __floats2bfloat162_rn(kv[6], kv[7]);
        *(uint4*)(d_K + (size_t)r * N + col0 + tx * 8) = pk.u;
    }
}

// ---------------------------------------------------------------------------
// Kernel 2: u-pass. u_i = MU / sum_j K_ij v_j.
// 4 rows per block (amortizes the v read). grid 2048, block 256.
// ---------------------------------------------------------------------------
__global__ __launch_bounds__(256) void u_pass_kernel()
{
    __shared__ float red[8][4];
    const int tid = threadIdx.x;
    const int row0 = blockIdx.x * 4;
    const uint4*  K8 = (const uint4*)d_K;
    const float4* v4 = (const float4*)d_v;

    float acc[4] = {0.0f, 0.0f, 0.0f, 0.0f};
#pragma unroll
    for (int it = 0; it < 4; ++it) {
        int i = tid + it * 256;                 // uint4 index within row
        float4 va = v4[2 * i];
        float4 vb = v4[2 * i + 1];
#pragma unroll
        for (int r = 0; r < 4; ++r) {
            union { uint4 u; __nv_bfloat162 h[4]; } k;
            k.u = K8[(size_t)(row0 + r) * (N / 8) + i];
            float2 c0 = __bfloat1622float2(k.h[0]);
            float2 c1 = __bfloat1622float2(k.h[1]);
            float2 c2 = __bfloat1622float2(k.h[2]);
            float2 c3 = __bfloat1622float2(k.h[3]);
            float s = acc[r];
            s = fmaf(c0.x, va.x, s); s = fmaf(c0.y, va.y, s);
            s = fmaf(c1.x, va.z, s); s = fmaf(c1.y, va.w, s);
            s = fmaf(c2.x, vb.x, s); s = fmaf(c2.y, vb.y, s);
            s = fmaf(c3.x, vb.z, s); s = fmaf(c3.y, vb.w, s);
            acc[r] = s;
        }
    }

#pragma unroll
    for (int r = 0; r < 4; ++r)
#pragma unroll
        for (int o = 16; o > 0; o >>= 1)
            acc[r] += __shfl_xor_sync(0xffffffffu, acc[r], o);

    if ((tid & 31) == 0) {
        int w = tid >> 5;
#pragma unroll
        for (int r = 0; r < 4; ++r) red[w][r] = acc[r];
    }
    __syncthreads();
    if (tid < 4) {
        float tot = red[0][tid];
#pragma unroll
        for (int w = 1; w < 8; ++w) tot += red[w][tid];
        d_u[row0 + tid] = MUVAL / tot;
    }
}

// ---------------------------------------------------------------------------
// Kernel 3: v-pass partials. colsum_j += sum over a 64-row strip of K_ij u_i.
// Each thread owns 8 consecutive columns (one uint4 of bf16).
// grid (4, 128), block 256. FIN: also accumulate t_j = sum (-log K)*K*u.
// ---------------------------------------------------------------------------
template <bool FIN>
__global__ __launch_bounds__(256) void v_partial_kernel()
{
    __shared__ float us[64];
    const int tid = threadIdx.x;
    const int i0 = blockIdx.y * 64;
    const int idx = blockIdx.x * 256 + tid;     // uint4 column index (8 cols)

    if (tid < 64) us[tid] = d_u[i0 + tid];
    __syncthreads();

    const uint4* K8 = (const uint4*)d_K;

    float acc[8];
    float tac[8];
#pragma unroll
    for (int c = 0; c < 8; ++c) { acc[c] = 0.0f; tac[c] = 0.0f; }

#pragma unroll 4
    for (int r = 0; r < 64; ++r) {
        union { uint4 u; __nv_bfloat162 h[4]; } k;
        k.u = K8[(size_t)(i0 + r) * (N / 8) + idx];
        float ur = us[r];
        float c[8];
        float2 t0 = __bfloat1622float2(k.h[0]);
        float2 t1 = __bfloat1622float2(k.h[1]);
        float2 t2 = __bfloat1622float2(k.h[2]);
        float2 t3 = __bfloat1622float2(k.h[3]);
        c[0] = t0.x; c[1] = t0.y; c[2] = t1.x; c[3] = t1.y;
        c[4] = t2.x; c[5] = t2.y; c[6] = t3.x; c[7] = t3.y;
#pragma unroll
        for (int j = 0; j < 8; ++j) {
            acc[j] = fmaf(c[j], ur, acc[j]);
            if (FIN) {
                // t += C * K * u, with C = -log K; K==0 entries contribute 0
                float kj = c[j];
                float term = (kj > 0.0f) ? (-__logf(kj)) * kj * ur : 0.0f;
                tac[j] += term;
            }
        }
    }

    float4* ps4 = (float4*)&d_ps[(size_t)blockIdx.y * N + (size_t)idx * 8];
    float4 o0, o1;
    o0.x = acc[0]; o0.y = acc[1]; o0.z = acc[2]; o0.w = acc[3];
    o1.x = acc[4]; o1.y = acc[5]; o1.z = acc[6]; o1.w = acc[7];
    ps4[0] = o0; ps4[1] = o1;
    if (FIN) {
        float4* pt4 = (float4*)&d_pt[(size_t)blockIdx.y * N + (size_t)idx * 8];
        float4 p0, p1;
        p0.x = tac[0]; p0.y = tac[1]; p0.z = tac[2]; p0.w = tac[3];
        p1.x = tac[4]; p1.y = tac[5]; p1.z = tac[6]; p1.w = tac[7];
        pt4[0] = p0; pt4[1] = p1;
    }
}

// ---------------------------------------------------------------------------
// Kernel 4: combine 128 strip partials -> v_j = NU / colsum_j.
// grid 32, block 256, one column per thread (coalesced across threads).
// ---------------------------------------------------------------------------
__global__ __launch_bounds__(256) void v_combine_kernel()
{
    const int j = blockIdx.x * 256 + threadIdx.x;
    float s = 0.0f;
#pragma unroll 8
    for (int k = 0; k < 128; ++k) s += d_ps[(size_t)k * N + j];
    d_v[j] = NUVAL / s;
}

// Final combine: also produce loss = sum_j v_j * t_j.
__global__ __launch_bounds__(256) void v_combine_final_kernel(float* __restrict__ out)
{
    __shared__ float reds[8];
    const int tid = threadIdx.x;
    const int j = blockIdx.x * 256 + tid;
    float s = 0.0f, t = 0.0f;
#pragma unroll 8
    for (int k = 0; k < 128; ++k) {
        s += d_ps[(size_t)k * N + j];
        t += d_pt[(size_t)k * N + j];
    }
    float vj = NUVAL / s;
    float lp = vj * t;
#pragma unroll
    for (int o = 16; o > 0; o >>= 1) lp += __shfl_xor_sync(0xffffffffu, lp, o);
    if ((tid & 31) == 0) reds[tid >> 5] = lp;
    __syncthreads();
    if (tid == 0) {
        float tot = reds[0];
#pragma unroll
        for (int w = 1; w < 8; ++w) tot += reds[w];
        atomicAdd(out, tot);
    }
}

// ---------------------------------------------------------------------------
extern "C" void kernel_launch(void* const* d_in, const int* in_sizes, int n_in,
                              void* d_out, int out_size)
{
    const float* x = (const float*)d_in[0];
    const float* y = (const float*)d_in[1];
    float* out = (float*)d_out;

    build_k_kernel<<<dim3(64, 64), 256>>>(x, y, out);

    for (int t = 0; t < 10; ++t) {
        u_pass_kernel<<<2048, 256>>>();
        if (t < 9) {
            v_partial_kernel<false><<<dim3(4, 128), 256>>>();
            v_combine_kernel<<<32, 256>>>();
        } else {
            v_partial_kernel<true><<<dim3(4, 128), 256>>>();
            v_combine_final_kernel<<<32, 256>>>(out);
        }
    }
}

// round 9
// speedup vs baseline: 2.5278x; 1.0730x over previous
#include <cuda_runtime.h>
#include <cuda_bf16.h>
#include <math.h>

#define N 8192
#define KD 32
#define STRIP 32
#define NSTRIPS (N / STRIP)     // 256

#define MUVAL (1.0f / 8192.0f)
#define NUVAL (1.0f / 8192.0f)

// Scratch (allocation-free: device globals)
__device__ __nv_bfloat16 d_K[(size_t)N * N];      // 128 MB: K = exp(-C) bf16
__device__ float d_v[N];                           // v = exp(g)
__device__ float d_ps[(size_t)NSTRIPS * N];        // column-sum partials (8 MB)
__device__ float d_pt[(size_t)NSTRIPS * N];        // loss partials (final iter)

// ---------------------------------------------------------------------------
// Kernel 1: build K = exp(-(|x_i|^2 + |y_j|^2 - 2 x_i.y_j)) in bf16.
// Also inits v = 1 and zeroes the output scalar.
// ---------------------------------------------------------------------------
__global__ __launch_bounds__(256) void build_k_kernel(
    const float* __restrict__ x, const float* __restrict__ y,
    float* __restrict__ out)
{
    __shared__ float xsT[KD][129];
    __shared__ float ysT[KD][129];
    __shared__ float xn[128];
    __shared__ float yn[128];

    const int tid = threadIdx.x;
    const int bx = blockIdx.x, by = blockIdx.y;
    const int row0 = by * 128, col0 = bx * 128;

    {
        int gid = (by * gridDim.x + bx) * 256 + tid;
        if (gid < N) d_v[gid] = 1.0f;
        if (gid == 0) out[0] = 0.0f;
    }

    const float4* x4 = (const float4*)(x + (size_t)row0 * KD);
    const float4* y4 = (const float4*)(y + (size_t)col0 * KD);
#pragma unroll
    for (int it = 0; it < 4; ++it) {
        int f = tid + it * 256;
        int r = f >> 3;
        int k = (f & 7) * 4;
        float4 vx = x4[f];
        xsT[k + 0][r] = vx.x; xsT[k + 1][r] = vx.y;
        xsT[k + 2][r] = vx.z; xsT[k + 3][r] = vx.w;
        float4 vy = y4[f];
        ysT[k + 0][r] = vy.x; ysT[k + 1][r] = vy.y;
        ysT[k + 2][r] = vy.z; ysT[k + 3][r] = vy.w;
    }
    __syncthreads();

    if (tid < 128) {
        float s = 0.0f;
#pragma unroll
        for (int k = 0; k < KD; ++k) { float a = xsT[k][tid]; s = fmaf(a, a, s); }
        xn[tid] = s;
    } else {
        int r = tid - 128;
        float s = 0.0f;
#pragma unroll
        for (int k = 0; k < KD; ++k) { float a = ysT[k][r]; s = fmaf(a, a, s); }
        yn[r] = s;
    }
    __syncthreads();

    const int tx = tid & 15;
    const int ty = tid >> 4;

    float acc[8][8];
#pragma unroll
    for (int i = 0; i < 8; ++i)
#pragma unroll
        for (int j = 0; j < 8; ++j) acc[i][j] = 0.0f;

#pragma unroll
    for (int k = 0; k < KD; ++k) {
        float a[8], b[8];
#pragma unroll
        for (int u = 0; u < 8; ++u) a[u] = xsT[k][ty * 8 + u];
#pragma unroll
        for (int u = 0; u < 8; ++u) b[u] = ysT[k][tx * 8 + u];
#pragma unroll
        for (int i = 0; i < 8; ++i)
#pragma unroll
            for (int j = 0; j < 8; ++j)
                acc[i][j] = fmaf(a[i], b[j], acc[i][j]);
    }

    float ynr[8];
#pragma unroll
    for (int j = 0; j < 8; ++j) ynr[j] = yn[tx * 8 + j];

#pragma unroll
    for (int i = 0; i < 8; ++i) {
        int r = row0 + ty * 8 + i;
        float xni = xn[ty * 8 + i];
        float kv[8];
#pragma unroll
        for (int j = 0; j < 8; ++j)
            kv[j] = __expf(2.0f * acc[i][j] - xni - ynr[j]);   // exp(-C)

        union { uint4 u; __nv_bfloat162 h[4]; } pk;
        pk.h[0] = __floats2bfloat162_rn(kv[0], kv[1]);
        pk.h[1] = __floats2bfloat162_rn(kv[2], kv[3]);
        pk.h[2] = __floats2bfloat162_rn(kv[4], kv[5]);
        pk.h[3] = __floats2bfloat162_rn(kv[6], kv[7]);
        *(uint4*)(d_K + (size_t)r * N + col0 + tx * 8) = pk.u;
    }
}

// ---------------------------------------------------------------------------
// Kernel 2 (fused sweep): block owns a 32-row strip of K.
//   Phase 1: u_i = MU / sum_j K_ij v_j     (strip from DRAM)
//   Phase 2: ps[strip][j] = sum_i K_ij u_i (strip re-read, should hit L2)
// grid NSTRIPS=256, block 512 (1 block/SM -> resident set 74 MB < L2).
// FIN: also t-partials sum_i (-log K) K u for the loss.
// ---------------------------------------------------------------------------
template <bool FIN>
__global__ __launch_bounds__(512, 1) void sweep_kernel()
{
    __shared__ float us[STRIP];

    const int tid = threadIdx.x;
    const int wrp = tid >> 5;            // 0..15
    const int lane = tid & 31;
    const int i0 = blockIdx.x * STRIP;

    const uint4*  K8 = (const uint4*)d_K;   // 1024 uint4 per row
    const float4* v4 = (const float4*)d_v;

    // ---- Phase 1: warp w handles rows i0+2w, i0+2w+1 ----
    {
        const int r0 = i0 + 2 * wrp;
        float a0 = 0.0f, a1 = 0.0f;
#pragma unroll 8
        for (int it = 0; it < 32; ++it) {
            int idx = lane + it * 32;                 // uint4 col index
            float4 va = v4[2 * idx];
            float4 vb = v4[2 * idx + 1];
            union { uint4 u; __nv_bfloat162 h[4]; } k0, k1;
            k0.u = K8[(size_t)r0 * (N / 8) + idx];
            k1.u = K8[(size_t)(r0 + 1) * (N / 8) + idx];
            float2 c;
            c = __bfloat1622float2(k0.h[0]); a0 = fmaf(c.x, va.x, a0); a0 = fmaf(c.y, va.y, a0);
            c = __bfloat1622float2(k0.h[1]); a0 = fmaf(c.x, va.z, a0); a0 = fmaf(c.y, va.w, a0);
            c = __bfloat1622float2(k0.h[2]); a0 = fmaf(c.x, vb.x, a0); a0 = fmaf(c.y, vb.y, a0);
            c = __bfloat1622float2(k0.h[3]); a0 = fmaf(c.x, vb.z, a0); a0 = fmaf(c.y, vb.w, a0);
            c = __bfloat1622float2(k1.h[0]); a1 = fmaf(c.x, va.x, a1); a1 = fmaf(c.y, va.y, a1);
            c = __bfloat1622float2(k1.h[1]); a1 = fmaf(c.x, va.z, a1); a1 = fmaf(c.y, va.w, a1);
            c = __bfloat1622float2(k1.h[2]); a1 = fmaf(c.x, vb.x, a1); a1 = fmaf(c.y, vb.y, a1);
            c = __bfloat1622float2(k1.h[3]); a1 = fmaf(c.x, vb.z, a1); a1 = fmaf(c.y, vb.w, a1);
        }
#pragma unroll
        for (int o = 16; o > 0; o >>= 1) {
            a0 += __shfl_xor_sync(0xffffffffu, a0, o);
            a1 += __shfl_xor_sync(0xffffffffu, a1, o);
        }
        if (lane == 0) {
            us[2 * wrp]     = MUVAL / a0;
            us[2 * wrp + 1] = MUVAL / a1;
        }
    }
    __syncthreads();

    // ---- Phase 2: column partials over the strip ----
#pragma unroll
    for (int half = 0; half < 2; ++half) {
        const int j4 = tid + half * 512;             // uint4 col index 0..1023
        float acc[8];
        float tac[8];
#pragma unroll
        for (int c = 0; c < 8; ++c) { acc[c] = 0.0f; tac[c] = 0.0f; }

#pragma unroll 4
        for (int r = 0; r < STRIP; ++r) {
            union { uint4 u; __nv_bfloat162 h[4]; } k;
            k.u = K8[(size_t)(i0 + r) * (N / 8) + j4];
            float ur = us[r];
            float c[8];
            float2 t0 = __bfloat1622float2(k.h[0]);
            float2 t1 = __bfloat1622float2(k.h[1]);
            float2 t2 = __bfloat1622float2(k.h[2]);
            float2 t3 = __bfloat1622float2(k.h[3]);
            c[0] = t0.x; c[1] = t0.y; c[2] = t1.x; c[3] = t1.y;
            c[4] = t2.x; c[5] = t2.y; c[6] = t3.x; c[7] = t3.y;
#pragma unroll
            for (int j = 0; j < 8; ++j) {
                acc[j] = fmaf(c[j], ur, acc[j]);
                if (FIN) {
                    float kj = c[j];
                    tac[j] += (kj > 0.0f) ? (-__logf(kj)) * kj * ur : 0.0f;
                }
            }
        }

        float4* ps4 = (float4*)&d_ps[(size_t)blockIdx.x * N + (size_t)j4 * 8];
        float4 o0, o1;
        o0.x = acc[0]; o0.y = acc[1]; o0.z = acc[2]; o0.w = acc[3];
        o1.x = acc[4]; o1.y = acc[5]; o1.z = acc[6]; o1.w = acc[7];
        ps4[0] = o0; ps4[1] = o1;
        if (FIN) {
            float4* pt4 = (float4*)&d_pt[(size_t)blockIdx.x * N + (size_t)j4 * 8];
            float4 p0, p1;
            p0.x = tac[0]; p0.y = tac[1]; p0.z = tac[2]; p0.w = tac[3];
            p1.x = tac[4]; p1.y = tac[5]; p1.z = tac[6]; p1.w = tac[7];
            pt4[0] = p0; pt4[1] = p1;
        }
    }
}

// ---------------------------------------------------------------------------
// Kernel 3: combine 256 strip partials -> v_j = NU / colsum_j.
// 4 threads per column (64 strips each) + smem reduce.
// grid 128, block 256 (64 columns per block).
// ---------------------------------------------------------------------------
__global__ __launch_bounds__(256) void v_combine_kernel()
{
    __shared__ float sm[4][64];
    const int tid = threadIdx.x;
    const int cl = tid & 63;
    const int g = tid >> 6;                       // 0..3
    const int j = blockIdx.x * 64 + cl;

    float s = 0.0f;
#pragma unroll 8
    for (int k = 0; k < 64; ++k)
        s += d_ps[(size_t)(g * 64 + k) * N + j];
    sm[g][cl] = s;
    __syncthreads();
    if (tid < 64) {
        float tot = sm[0][tid] + sm[1][tid] + sm[2][tid] + sm[3][tid];
        d_v[blockIdx.x * 64 + tid] = NUVAL / tot;
    }
}

// Final combine: also loss = sum_j v_j * t_j.
__global__ __launch_bounds__(256) void v_combine_final_kernel(float* __restrict__ out)
{
    __shared__ float sm[4][64];
    __shared__ float smt[4][64];
    __shared__ float reds[2];
    const int tid = threadIdx.x;
    const int cl = tid & 63;
    const int g = tid >> 6;
    const int j = blockIdx.x * 64 + cl;

    float s = 0.0f, t = 0.0f;
#pragma unroll 8
    for (int k = 0; k < 64; ++k) {
        s += d_ps[(size_t)(g * 64 + k) * N + j];
        t += d_pt[(size_t)(g * 64 + k) * N + j];
    }
    sm[g][cl] = s;
    smt[g][cl] = t;
    __syncthreads();
    if (tid < 64) {
        float tot = sm[0][tid] + sm[1][tid] + sm[2][tid] + sm[3][tid];
        float tt  = smt[0][tid] + smt[1][tid] + smt[2][tid] + smt[3][tid];
        float lp = (NUVAL / tot) * tt;
#pragma unroll
        for (int o = 16; o > 0; o >>= 1) lp += __shfl_xor_sync(0xffffffffu, lp, o);
        if ((tid & 31) == 0) reds[tid >> 5] = lp;
    }
    __syncthreads();
    if (tid == 0) atomicAdd(out, reds[0] + reds[1]);
}

// ---------------------------------------------------------------------------
extern "C" void kernel_launch(void* const* d_in, const int* in_sizes, int n_in,
                              void* d_out, int out_size)
{
    const float* x = (const float*)d_in[0];
    const float* y = (const float*)d_in[1];
    float* out = (float*)d_out;

    build_k_kernel<<<dim3(64, 64), 256>>>(x, y, out);

    for (int t = 0; t < 10; ++t) {
        if (t < 9) {
            sweep_kernel<false><<<NSTRIPS, 512>>>();
            v_combine_kernel<<<N / 64, 256>>>();
        } else {
            sweep_kernel<true><<<NSTRIPS, 512>>>();
            v_combine_final_kernel<<<N / 64, 256>>>(out);
        }
    }
}

// round 10
// speedup vs baseline: 2.7593x; 1.0915x over previous
#include <cuda_runtime.h>
#include <cuda_bf16.h>
#include <math.h>

#define N 8192
#define KD 32
#define STRIP 32
#define NSTRIPS (N / STRIP)     // 256

#define MUVAL (1.0f / 8192.0f)
#define NUVAL (1.0f / 8192.0f)

// Scratch (allocation-free: device globals)
__device__ __nv_bfloat16 d_K[(size_t)N * N];      // 128 MB: K = exp(-C) bf16
__device__ float d_v[N];                           // v = exp(g)
__device__ float d_ps[(size_t)NSTRIPS * N];        // column-sum partials (8 MB)
__device__ float d_pt[(size_t)NSTRIPS * N];        // loss partials (final iter)

// ---------------------------------------------------------------------------
// Kernel 1: build K = exp(-(|x_i|^2 + |y_j|^2 - 2 x_i.y_j)) in bf16.
// Also inits v = 1 and zeroes the output scalar.
// ---------------------------------------------------------------------------
__global__ __launch_bounds__(256) void build_k_kernel(
    const float* __restrict__ x, const float* __restrict__ y,
    float* __restrict__ out)
{
    __shared__ float xsT[KD][129];
    __shared__ float ysT[KD][129];
    __shared__ float xn[128];
    __shared__ float yn[128];

    const int tid = threadIdx.x;
    const int bx = blockIdx.x, by = blockIdx.y;
    const int row0 = by * 128, col0 = bx * 128;

    {
        int gid = (by * gridDim.x + bx) * 256 + tid;
        if (gid < N) d_v[gid] = 1.0f;
        if (gid == 0) out[0] = 0.0f;
    }

    const float4* x4 = (const float4*)(x + (size_t)row0 * KD);
    const float4* y4 = (const float4*)(y + (size_t)col0 * KD);
#pragma unroll
    for (int it = 0; it < 4; ++it) {
        int f = tid + it * 256;
        int r = f >> 3;
        int k = (f & 7) * 4;
        float4 vx = x4[f];
        xsT[k + 0][r] = vx.x; xsT[k + 1][r] = vx.y;
        xsT[k + 2][r] = vx.z; xsT[k + 3][r] = vx.w;
        float4 vy = y4[f];
        ysT[k + 0][r] = vy.x; ysT[k + 1][r] = vy.y;
        ysT[k + 2][r] = vy.z; ysT[k + 3][r] = vy.w;
    }
    __syncthreads();

    if (tid < 128) {
        float s = 0.0f;
#pragma unroll
        for (int k = 0; k < KD; ++k) { float a = xsT[k][tid]; s = fmaf(a, a, s); }
        xn[tid] = s;
    } else {
        int r = tid - 128;
        float s = 0.0f;
#pragma unroll
        for (int k = 0; k < KD; ++k) { float a = ysT[k][r]; s = fmaf(a, a, s); }
        yn[r] = s;
    }
    __syncthreads();

    const int tx = tid & 15;
    const int ty = tid >> 4;

    float acc[8][8];
#pragma unroll
    for (int i = 0; i < 8; ++i)
#pragma unroll
        for (int j = 0; j < 8; ++j) acc[i][j] = 0.0f;

#pragma unroll
    for (int k = 0; k < KD; ++k) {
        float a[8], b[8];
#pragma unroll
        for (int u = 0; u < 8; ++u) a[u] = xsT[k][ty * 8 + u];
#pragma unroll
        for (int u = 0; u < 8; ++u) b[u] = ysT[k][tx * 8 + u];
#pragma unroll
        for (int i = 0; i < 8; ++i)
#pragma unroll
            for (int j = 0; j < 8; ++j)
                acc[i][j] = fmaf(a[i], b[j], acc[i][j]);
    }

    float ynr[8];
#pragma unroll
    for (int j = 0; j < 8; ++j) ynr[j] = yn[tx * 8 + j];

#pragma unroll
    for (int i = 0; i < 8; ++i) {
        int r = row0 + ty * 8 + i;
        float xni = xn[ty * 8 + i];
        float kv[8];
#pragma unroll
        for (int j = 0; j < 8; ++j)
            kv[j] = __expf(2.0f * acc[i][j] - xni - ynr[j]);   // exp(-C)

        union { uint4 u; __nv_bfloat162 h[4]; } pk;
        pk.h[0] = __floats2bfloat162_rn(kv[0], kv[1]);
        pk.h[1] = __floats2bfloat162_rn(kv[2], kv[3]);
        pk.h[2] = __floats2bfloat162_rn(kv[4], kv[5]);
        pk.h[3] = __floats2bfloat162_rn(kv[6], kv[7]);
        *(uint4*)(d_K + (size_t)r * N + col0 + tx * 8) = pk.u;
    }
}

// ---------------------------------------------------------------------------
// Kernel 2 (fused sweep): block owns a 32-row strip of K.
//   Phase 1: u_i = MU / sum_j K_ij v_j     (strip from DRAM; 1 warp / row)
//   Phase 2: ps[strip][j] = sum_i K_ij u_i (strip re-read, hits L2;
//            1 uint4-column / thread)
// grid NSTRIPS=256, block 1024 (32 warps -> ~50% occ for latency cover;
// still 1 block/SM so resident set 74 MB < L2).
// FIN: also t-partials sum_i (-log K) K u for the loss.
// ---------------------------------------------------------------------------
template <bool FIN>
__global__ __launch_bounds__(1024, 1) void sweep_kernel()
{
    __shared__ float us[STRIP];

    const int tid = threadIdx.x;
    const int wrp = tid >> 5;            // 0..31
    const int lane = tid & 31;
    const int i0 = blockIdx.x * STRIP;

    const uint4*  K8 = (const uint4*)d_K;   // 1024 uint4 per row
    const float4* v4 = (const float4*)d_v;

    // ---- Phase 1: warp w handles row i0+w ----
    {
        const int r0 = i0 + wrp;
        const uint4* Kr = K8 + (size_t)r0 * (N / 8);
        float a0 = 0.0f;
#pragma unroll 8
        for (int it = 0; it < 32; ++it) {
            int idx = lane + it * 32;                 // uint4 col index
            float4 va = v4[2 * idx];
            float4 vb = v4[2 * idx + 1];
            union { uint4 u; __nv_bfloat162 h[4]; } k0;
            k0.u = Kr[idx];
            float2 c;
            c = __bfloat1622float2(k0.h[0]); a0 = fmaf(c.x, va.x, a0); a0 = fmaf(c.y, va.y, a0);
            c = __bfloat1622float2(k0.h[1]); a0 = fmaf(c.x, va.z, a0); a0 = fmaf(c.y, va.w, a0);
            c = __bfloat1622float2(k0.h[2]); a0 = fmaf(c.x, vb.x, a0); a0 = fmaf(c.y, vb.y, a0);
            c = __bfloat1622float2(k0.h[3]); a0 = fmaf(c.x, vb.z, a0); a0 = fmaf(c.y, vb.w, a0);
        }
#pragma unroll
        for (int o = 16; o > 0; o >>= 1)
            a0 += __shfl_xor_sync(0xffffffffu, a0, o);
        if (lane == 0) us[wrp] = MUVAL / a0;
    }
    __syncthreads();

    // ---- Phase 2: column partials over the strip; 1 uint4 col / thread ----
    {
        const int j4 = tid;                          // uint4 col index 0..1023
        float acc[8];
        float tac[8];
#pragma unroll
        for (int c = 0; c < 8; ++c) { acc[c] = 0.0f; tac[c] = 0.0f; }

#pragma unroll 4
        for (int r = 0; r < STRIP; ++r) {
            union { uint4 u; __nv_bfloat162 h[4]; } k;
            k.u = K8[(size_t)(i0 + r) * (N / 8) + j4];
            float ur = us[r];
            float c[8];
            float2 t0 = __bfloat1622float2(k.h[0]);
            float2 t1 = __bfloat1622float2(k.h[1]);
            float2 t2 = __bfloat1622float2(k.h[2]);
            float2 t3 = __bfloat1622float2(k.h[3]);
            c[0] = t0.x; c[1] = t0.y; c[2] = t1.x; c[3] = t1.y;
            c[4] = t2.x; c[5] = t2.y; c[6] = t3.x; c[7] = t3.y;
#pragma unroll
            for (int j = 0; j < 8; ++j) {
                acc[j] = fmaf(c[j], ur, acc[j]);
                if (FIN) {
                    float kj = c[j];
                    tac[j] += (kj > 0.0f) ? (-__logf(kj)) * kj * ur : 0.0f;
                }
            }
        }

        float4* ps4 = (float4*)&d_ps[(size_t)blockIdx.x * N + (size_t)j4 * 8];
        float4 o0, o1;
        o0.x = acc[0]; o0.y = acc[1]; o0.z = acc[2]; o0.w = acc[3];
        o1.x = acc[4]; o1.y = acc[5]; o1.z = acc[6]; o1.w = acc[7];
        ps4[0] = o0; ps4[1] = o1;
        if (FIN) {
            float4* pt4 = (float4*)&d_pt[(size_t)blockIdx.x * N + (size_t)j4 * 8];
            float4 p0, p1;
            p0.x = tac[0]; p0.y = tac[1]; p0.z = tac[2]; p0.w = tac[3];
            p1.x = tac[4]; p1.y = tac[5]; p1.z = tac[6]; p1.w = tac[7];
            pt4[0] = p0; pt4[1] = p1;
        }
    }
}

// ---------------------------------------------------------------------------
// Kernel 3: combine 256 strip partials -> v_j = NU / colsum_j.
// 4 threads per column (64 strips each) + smem reduce.
// grid 128, block 256 (64 columns per block).
// ---------------------------------------------------------------------------
__global__ __launch_bounds__(256) void v_combine_kernel()
{
    __shared__ float sm[4][64];
    const int tid = threadIdx.x;
    const int cl = tid & 63;
    const int g = tid >> 6;                       // 0..3
    const int j = blockIdx.x * 64 + cl;

    float s = 0.0f;
#pragma unroll 8
    for (int k = 0; k < 64; ++k)
        s += d_ps[(size_t)(g * 64 + k) * N + j];
    sm[g][cl] = s;
    __syncthreads();
    if (tid < 64) {
        float tot = sm[0][tid] + sm[1][tid] + sm[2][tid] + sm[3][tid];
        d_v[blockIdx.x * 64 + tid] = NUVAL / tot;
    }
}

// Final combine: also loss = sum_j v_j * t_j.
__global__ __launch_bounds__(256) void v_combine_final_kernel(float* __restrict__ out)
{
    __shared__ float sm[4][64];
    __shared__ float smt[4][64];
    __shared__ float reds[2];
    const int tid = threadIdx.x;
    const int cl = tid & 63;
    const int g = tid >> 6;
    const int j = blockIdx.x * 64 + cl;

    float s = 0.0f, t = 0.0f;
#pragma unroll 8
    for (int k = 0; k < 64; ++k) {
        s += d_ps[(size_t)(g * 64 + k) * N + j];
        t += d_pt[(size_t)(g * 64 + k) * N + j];
    }
    sm[g][cl] = s;
    smt[g][cl] = t;
    __syncthreads();
    if (tid < 64) {
        float tot = sm[0][tid] + sm[1][tid] + sm[2][tid] + sm[3][tid];
        float tt  = smt[0][tid] + smt[1][tid] + smt[2][tid] + smt[3][tid];
        float lp = (NUVAL / tot) * tt;
#pragma unroll
        for (int o = 16; o > 0; o >>= 1) lp += __shfl_xor_sync(0xffffffffu, lp, o);
        if ((tid & 31) == 0) reds[tid >> 5] = lp;
    }
    __syncthreads();
    if (tid == 0) atomicAdd(out, reds[0] + reds[1]);
}

// ---------------------------------------------------------------------------
extern "C" void kernel_launch(void* const* d_in, const int* in_sizes, int n_in,
                              void* d_out, int out_size)
{
    const float* x = (const float*)d_in[0];
    const float* y = (const float*)d_in[1];
    float* out = (float*)d_out;

    build_k_kernel<<<dim3(64, 64), 256>>>(x, y, out);

    for (int t = 0; t < 10; ++t) {
        if (t < 9) {
            sweep_kernel<false><<<NSTRIPS, 1024>>>();
            v_combine_kernel<<<N / 64, 256>>>();
        } else {
            sweep_kernel<true><<<NSTRIPS, 1024>>>();
            v_combine_final_kernel<<<N / 64, 256>>>(out);
        }
    }
}